// round 1
// baseline (speedup 1.0000x reference)
#include <cuda_runtime.h>
#include <math.h>
#include <stdint.h>

#define N_NODES 100000
#define N_EDGES 800000

// ---------------- scratch (static __device__ — no allocations allowed) ----------
__device__ float g_AB[(size_t)N_NODES * 256];    // [n][0:128]=x@W1a, [n][128:256]=x@W1b
__device__ float g_Hagg[(size_t)N_NODES * 128];  // sum over in-edges of relu(h)
__device__ float g_G[(size_t)N_NODES * 128];     // relu(update hidden)
__device__ float g_deg[N_NODES];                 // in-degree (float)
__device__ float g_Wcat[192 * 128];              // [U1a (64x128) ; V = W2@U1b (128x128)]
__device__ float g_dvec[128];                    // b2 @ U1b

// ---------------- prep: build Wcat and dvec --------------------------------------
__global__ void prep_kernel(const float* __restrict__ W2, const float* __restrict__ b2,
                            const float* __restrict__ U1) {
    int b = blockIdx.x, j = threadIdx.x;  // 128 threads
    if (b < 64) {
        g_Wcat[b * 128 + j] = U1[b * 128 + j];                 // U1a row b
    } else if (b < 192) {
        int i = b - 64;                                        // V row i
        float s = 0.f;
#pragma unroll
        for (int k = 0; k < 64; k++)
            s = fmaf(W2[i * 64 + k], U1[(64 + k) * 128 + j], s);
        g_Wcat[b * 128 + j] = s;
    } else {
        float s = 0.f;
#pragma unroll
        for (int k = 0; k < 64; k++)
            s = fmaf(b2[k], U1[(64 + k) * 128 + j], s);
        g_dvec[j] = s;
    }
}

// ---------------- zero scratch accumulators ---------------------------------------
__global__ void zero_kernel() {
    size_t idx = (size_t)blockIdx.x * blockDim.x + threadIdx.x;
    size_t stride = (size_t)gridDim.x * blockDim.x;
    size_t tot4 = (size_t)N_NODES * 128 / 4;
    float4 z = make_float4(0.f, 0.f, 0.f, 0.f);
    for (size_t i = idx; i < tot4; i += stride) ((float4*)g_Hagg)[i] = z;
    for (size_t i = idx; i < (size_t)N_NODES; i += stride) g_deg[i] = 0.f;
}

// ---------------- GEMM1: AB = x @ [W1a | W1b]   (M=100000, K=64, N=2x128) ---------
__global__ __launch_bounds__(256) void gemm_ab_kernel(const float* __restrict__ x,
                                                      const float* __restrict__ W1) {
    __shared__ float As[32][65];
    __shared__ float Bs[32][128];
    int row0 = blockIdx.x * 64;
    int cb = blockIdx.y;  // 0: W1 rows 0..63 (x_src part), 1: rows 64..127 (x_dst part)
    const float* Wb = W1 + (size_t)cb * 64 * 128;
    int tid = threadIdx.x;
    int r0 = (tid >> 4) * 4;
    int c0 = (tid & 15) * 8;
    float acc[4][8];
#pragma unroll
    for (int i = 0; i < 4; i++)
#pragma unroll
        for (int j = 0; j < 8; j++) acc[i][j] = 0.f;

    for (int k0 = 0; k0 < 64; k0 += 32) {
#pragma unroll
        for (int it = 0; it < 8; it++) {
            int t = tid + it * 256;
            int k = t & 31, m = t >> 5;
            int gm = row0 + m;
            As[k][m] = (gm < N_NODES) ? x[(size_t)gm * 64 + k0 + k] : 0.f;
        }
#pragma unroll
        for (int it = 0; it < 4; it++) {
            int t = tid + it * 256;
            int k = t >> 5, j4 = t & 31;
            *(float4*)&Bs[k][j4 * 4] = *(const float4*)(Wb + (size_t)(k0 + k) * 128 + j4 * 4);
        }
        __syncthreads();
#pragma unroll
        for (int k = 0; k < 32; k++) {
            float a0 = As[k][r0], a1 = As[k][r0 + 1], a2 = As[k][r0 + 2], a3 = As[k][r0 + 3];
            float4 bv0 = *(float4*)&Bs[k][c0];
            float4 bv1 = *(float4*)&Bs[k][c0 + 4];
            float bj[8] = {bv0.x, bv0.y, bv0.z, bv0.w, bv1.x, bv1.y, bv1.z, bv1.w};
#pragma unroll
            for (int j = 0; j < 8; j++) {
                acc[0][j] = fmaf(a0, bj[j], acc[0][j]);
                acc[1][j] = fmaf(a1, bj[j], acc[1][j]);
                acc[2][j] = fmaf(a2, bj[j], acc[2][j]);
                acc[3][j] = fmaf(a3, bj[j], acc[3][j]);
            }
        }
        __syncthreads();
    }
#pragma unroll
    for (int i = 0; i < 4; i++) {
        int gm = row0 + r0 + i;
        if (gm < N_NODES) {
            float* o = g_AB + (size_t)gm * 256 + cb * 128 + c0;
            *(float4*)o = make_float4(acc[i][0], acc[i][1], acc[i][2], acc[i][3]);
            *(float4*)(o + 4) = make_float4(acc[i][4], acc[i][5], acc[i][6], acc[i][7]);
        }
    }
}

// ---------------- edge kernel: h=relu(A[src]+B[dst]+log1p(ef)@W1c+b1), RED into Hagg
__global__ __launch_bounds__(256) void edge_kernel(const int* __restrict__ ei,
                                                   const float* __restrict__ ef,
                                                   const float* __restrict__ W1,
                                                   const float* __restrict__ b1) {
    __shared__ float s_wc[512];   // W1 rows 128..131 (edge-feature rows)
    __shared__ float s_b1[128];
    for (int t = threadIdx.x; t < 512; t += 256) s_wc[t] = W1[128 * 128 + t];
    if (threadIdx.x < 128) s_b1[threadIdx.x] = b1[threadIdx.x];
    __syncthreads();

    int warp = threadIdx.x >> 5;
    int lane = threadIdx.x & 31;
    int e = blockIdx.x * 8 + warp;
    if (e >= N_EDGES) return;
    int src = ei[e];
    int dst = ei[N_EDGES + e];

    float mv = 0.f;
    if (lane < 4) mv = log1pf(ef[(size_t)e * 4 + lane]);
    float l0 = __shfl_sync(0xffffffffu, mv, 0);
    float l1 = __shfl_sync(0xffffffffu, mv, 1);
    float l2 = __shfl_sync(0xffffffffu, mv, 2);
    float l3 = __shfl_sync(0xffffffffu, mv, 3);

    float4 a = *(const float4*)(g_AB + (size_t)src * 256 + lane * 4);
    float4 b = *(const float4*)(g_AB + (size_t)dst * 256 + 128 + lane * 4);
    float4 w0 = *(const float4*)&s_wc[0 * 128 + lane * 4];
    float4 w1 = *(const float4*)&s_wc[1 * 128 + lane * 4];
    float4 w2 = *(const float4*)&s_wc[2 * 128 + lane * 4];
    float4 w3 = *(const float4*)&s_wc[3 * 128 + lane * 4];
    float4 bb = *(const float4*)&s_b1[lane * 4];

    float4 h;
    h.x = fmaxf(fmaf(l3, w3.x, fmaf(l2, w2.x, fmaf(l1, w1.x, fmaf(l0, w0.x, a.x + b.x + bb.x)))), 0.f);
    h.y = fmaxf(fmaf(l3, w3.y, fmaf(l2, w2.y, fmaf(l1, w1.y, fmaf(l0, w0.y, a.y + b.y + bb.y)))), 0.f);
    h.z = fmaxf(fmaf(l3, w3.z, fmaf(l2, w2.z, fmaf(l1, w1.z, fmaf(l0, w0.z, a.z + b.z + bb.z)))), 0.f);
    h.w = fmaxf(fmaf(l3, w3.w, fmaf(l2, w2.w, fmaf(l1, w1.w, fmaf(l0, w0.w, a.w + b.w + bb.w)))), 0.f);

    atomicAdd((float4*)(g_Hagg + (size_t)dst * 128 + lane * 4), h);  // sm_90+ vector RED
    if (lane == 0) atomicAdd(&g_deg[dst], 1.0f);
}

// ---------------- GEMM2: G = relu([x|Hagg] @ Wcat + deg*dvec + bu1)  (K=192, N=128)
__global__ __launch_bounds__(256) void gemm_upd1_kernel(const float* __restrict__ x,
                                                        const float* __restrict__ bu1) {
    __shared__ float As[32][65];
    __shared__ float Bs[32][128];
    int row0 = blockIdx.x * 64;
    int tid = threadIdx.x;
    int r0 = (tid >> 4) * 4;
    int c0 = (tid & 15) * 8;
    float acc[4][8];
#pragma unroll
    for (int i = 0; i < 4; i++)
#pragma unroll
        for (int j = 0; j < 8; j++) acc[i][j] = 0.f;

    for (int k0 = 0; k0 < 192; k0 += 32) {
        bool isx = (k0 < 64);
#pragma unroll
        for (int it = 0; it < 8; it++) {
            int t = tid + it * 256;
            int k = t & 31, m = t >> 5;
            int gm = row0 + m;
            float v = 0.f;
            if (gm < N_NODES) {
                int gk = k0 + k;
                v = isx ? x[(size_t)gm * 64 + gk] : g_Hagg[(size_t)gm * 128 + (gk - 64)];
            }
            As[k][m] = v;
        }
#pragma unroll
        for (int it = 0; it < 4; it++) {
            int t = tid + it * 256;
            int k = t >> 5, j4 = t & 31;
            *(float4*)&Bs[k][j4 * 4] = *(const float4*)(g_Wcat + (size_t)(k0 + k) * 128 + j4 * 4);
        }
        __syncthreads();
#pragma unroll
        for (int k = 0; k < 32; k++) {
            float a0 = As[k][r0], a1 = As[k][r0 + 1], a2 = As[k][r0 + 2], a3 = As[k][r0 + 3];
            float4 bv0 = *(float4*)&Bs[k][c0];
            float4 bv1 = *(float4*)&Bs[k][c0 + 4];
            float bj[8] = {bv0.x, bv0.y, bv0.z, bv0.w, bv1.x, bv1.y, bv1.z, bv1.w};
#pragma unroll
            for (int j = 0; j < 8; j++) {
                acc[0][j] = fmaf(a0, bj[j], acc[0][j]);
                acc[1][j] = fmaf(a1, bj[j], acc[1][j]);
                acc[2][j] = fmaf(a2, bj[j], acc[2][j]);
                acc[3][j] = fmaf(a3, bj[j], acc[3][j]);
            }
        }
        __syncthreads();
    }
    float4 d0 = *(const float4*)(g_dvec + c0);
    float4 d1 = *(const float4*)(g_dvec + c0 + 4);
    float4 u0 = *(const float4*)(bu1 + c0);
    float4 u1 = *(const float4*)(bu1 + c0 + 4);
    float dvv[8] = {d0.x, d0.y, d0.z, d0.w, d1.x, d1.y, d1.z, d1.w};
    float uvv[8] = {u0.x, u0.y, u0.z, u0.w, u1.x, u1.y, u1.z, u1.w};
#pragma unroll
    for (int i = 0; i < 4; i++) {
        int gm = row0 + r0 + i;
        if (gm < N_NODES) {
            float dg = g_deg[gm];
            float o[8];
#pragma unroll
            for (int j = 0; j < 8; j++)
                o[j] = fmaxf(acc[i][j] + fmaf(dg, dvv[j], uvv[j]), 0.f);
            float* op = g_G + (size_t)gm * 128 + c0;
            *(float4*)op = make_float4(o[0], o[1], o[2], o[3]);
            *(float4*)(op + 4) = make_float4(o[4], o[5], o[6], o[7]);
        }
    }
}

// ---------------- GEMM3: out = G @ U2 + bu2   (K=128, N=64) -----------------------
__global__ __launch_bounds__(256) void gemm_upd2_kernel(const float* __restrict__ U2,
                                                        const float* __restrict__ bu2,
                                                        float* __restrict__ out) {
    __shared__ float As[32][65];
    __shared__ float Bs[32][64];
    int row0 = blockIdx.x * 64;
    int tid = threadIdx.x;
    int r0 = (tid >> 4) * 4;
    int c0 = (tid & 15) * 4;
    float acc[4][4];
#pragma unroll
    for (int i = 0; i < 4; i++)
#pragma unroll
        for (int j = 0; j < 4; j++) acc[i][j] = 0.f;

    for (int k0 = 0; k0 < 128; k0 += 32) {
#pragma unroll
        for (int it = 0; it < 8; it++) {
            int t = tid + it * 256;
            int k = t & 31, m = t >> 5;
            int gm = row0 + m;
            As[k][m] = (gm < N_NODES) ? g_G[(size_t)gm * 128 + k0 + k] : 0.f;
        }
#pragma unroll
        for (int it = 0; it < 2; it++) {
            int t = tid + it * 256;
            int k = t >> 4, j4 = t & 15;
            *(float4*)&Bs[k][j4 * 4] = *(const float4*)(U2 + (size_t)(k0 + k) * 64 + j4 * 4);
        }
        __syncthreads();
#pragma unroll
        for (int k = 0; k < 32; k++) {
            float a0 = As[k][r0], a1 = As[k][r0 + 1], a2 = As[k][r0 + 2], a3 = As[k][r0 + 3];
            float4 bv = *(float4*)&Bs[k][c0];
            float bj[4] = {bv.x, bv.y, bv.z, bv.w};
#pragma unroll
            for (int j = 0; j < 4; j++) {
                acc[0][j] = fmaf(a0, bj[j], acc[0][j]);
                acc[1][j] = fmaf(a1, bj[j], acc[1][j]);
                acc[2][j] = fmaf(a2, bj[j], acc[2][j]);
                acc[3][j] = fmaf(a3, bj[j], acc[3][j]);
            }
        }
        __syncthreads();
    }
    float4 bv = *(const float4*)(bu2 + c0);
    float bb[4] = {bv.x, bv.y, bv.z, bv.w};
#pragma unroll
    for (int i = 0; i < 4; i++) {
        int gm = row0 + r0 + i;
        if (gm < N_NODES) {
            *(float4*)(out + (size_t)gm * 64 + c0) =
                make_float4(acc[i][0] + bb[0], acc[i][1] + bb[1],
                            acc[i][2] + bb[2], acc[i][3] + bb[3]);
        }
    }
}

// ---------------- launch ----------------------------------------------------------
extern "C" void kernel_launch(void* const* d_in, const int* in_sizes, int n_in,
                              void* d_out, int out_size) {
    const float* x   = (const float*)d_in[0];
    const int*   ei  = (const int*)d_in[1];
    const float* ef  = (const float*)d_in[2];
    const float* W1  = (const float*)d_in[3];
    const float* b1  = (const float*)d_in[4];
    const float* W2  = (const float*)d_in[5];
    const float* b2  = (const float*)d_in[6];
    const float* U1  = (const float*)d_in[7];
    const float* bu1 = (const float*)d_in[8];
    const float* U2  = (const float*)d_in[9];
    const float* bu2 = (const float*)d_in[10];
    float* out = (float*)d_out;

    prep_kernel<<<193, 128>>>(W2, b2, U1);
    zero_kernel<<<1184, 256>>>();
    gemm_ab_kernel<<<dim3(1563, 2), 256>>>(x, W1);
    edge_kernel<<<(N_EDGES + 7) / 8, 256>>>(ei, ef, W1, b1);
    gemm_upd1_kernel<<<1563, 256>>>(x, bu1);
    gemm_upd2_kernel<<<1563, 256>>>(U2, bu2, out);
}